// round 8
// baseline (speedup 1.0000x reference)
#include <cuda_runtime.h>
#include <cuda_fp16.h>
#include <cstdint>
#include <cstddef>

// Problem constants
#define EE   384
#define HH   6
#define HSS  64
#define BB   64
#define TT   256
#define FFD  1536
#define NROWS (BB*TT)          // 16384

// ---------------- scratch (device globals; no allocation allowed) ----------
__device__ __half g_qkv_h[(size_t)NROWS * 3 * EE];
__device__ __half g_kv_h[(size_t)NROWS * 2 * EE];
__device__ __half g_q_h[(size_t)NROWS * EE];
__device__ __half g_att_h[(size_t)NROWS * EE];
__device__ __half g_hid_h[(size_t)NROWS * FFD];
__device__ __half g_xh[(size_t)NROWS * EE];
__device__ __half g_ench[(size_t)NROWS * EE];
__device__ __half g_po1h[(size_t)NROWS * EE];
__device__ __half g_po2h[(size_t)NROWS * EE];
__device__ float  g_buf[(size_t)NROWS * EE];
__device__ float  g_o1[(size_t)NROWS * EE];
__device__ float  g_o2[(size_t)NROWS * EE];
// fp16 weights, transposed to [out][in]
__device__ __half g_wqkvh[3 * EE * EE];
__device__ __half g_wq2h[EE * EE];
__device__ __half g_wkvh[2 * EE * EE];
__device__ __half g_wp1h[EE * EE];
__device__ __half g_wp2h[EE * EE];
__device__ __half g_wf1h[FFD * EE];
__device__ __half g_wf2h[EE * FFD];
__device__ float  g_bqkv[3 * EE];
__device__ float  g_bkv[2 * EE];
__device__ float  g_bq2[EE];

// ---------------- PTX helpers ----------------------------------------------
__device__ __forceinline__ uint32_t smem_u32(const void* p) {
    uint32_t a;
    asm("{ .reg .u64 t; cvta.to.shared.u64 t, %1; cvt.u32.u64 %0, t; }" : "=r"(a) : "l"(p));
    return a;
}
__device__ __forceinline__ void cp16(uint32_t dst, const void* src) {
    asm volatile("cp.async.cg.shared.global [%0], [%1], 16;" :: "r"(dst), "l"(src));
}
__device__ __forceinline__ void ldsm4(uint32_t& r0, uint32_t& r1, uint32_t& r2, uint32_t& r3,
                                      uint32_t addr) {
    asm volatile("ldmatrix.sync.aligned.m8n8.x4.shared.b16 {%0,%1,%2,%3}, [%4];"
                 : "=r"(r0), "=r"(r1), "=r"(r2), "=r"(r3) : "r"(addr));
}
__device__ __forceinline__ void ldsm4t(uint32_t& r0, uint32_t& r1, uint32_t& r2, uint32_t& r3,
                                       uint32_t addr) {
    asm volatile("ldmatrix.sync.aligned.m8n8.x4.trans.shared.b16 {%0,%1,%2,%3}, [%4];"
                 : "=r"(r0), "=r"(r1), "=r"(r2), "=r"(r3) : "r"(addr));
}
__device__ __forceinline__ void mma16816(float* c, const uint32_t* a, const uint32_t* b) {
    asm volatile(
        "mma.sync.aligned.m16n8k16.row.col.f32.f16.f16.f32 "
        "{%0,%1,%2,%3}, {%4,%5,%6,%7}, {%8,%9}, {%0,%1,%2,%3};"
        : "+f"(c[0]), "+f"(c[1]), "+f"(c[2]), "+f"(c[3])
        : "r"(a[0]), "r"(a[1]), "r"(a[2]), "r"(a[3]), "r"(b[0]), "r"(b[1]));
}
__device__ __forceinline__ uint32_t ph2(float a, float b) {
    __half2 h = __floats2half2_rn(a, b);
    return *reinterpret_cast<uint32_t*>(&h);
}
__device__ __forceinline__ uint32_t sw_off(int r, int seg) {
    return (uint32_t)(r * 128 + (((seg ^ (r & 7)) & 7) << 4));
}

// ---------------- megapack --------------------------------------------------
#define HPK 147456
#define S_ATTNW (6*HPK)
#define S_PROJ  (2*HPK)
#define S_FF    (EE*FFD)
#define NACT    ((size_t)NROWS*EE)
#define NACTV   ((long long)(NACT/4))
#define PACK_TOTAL ((long long)S_ATTNW + S_PROJ + 2*S_FF + 3*EE + 2*EE + EE + 2*NACTV)

__global__ void megapack_kernel(
    const float* __restrict__ wq1, const float* __restrict__ wk1, const float* __restrict__ wv1,
    const float* __restrict__ wq2, const float* __restrict__ wk2, const float* __restrict__ wv2,
    const float* __restrict__ pw1, const float* __restrict__ pw2,
    const float* __restrict__ fw1, const float* __restrict__ fw2,
    const float* __restrict__ bq1, const float* __restrict__ bk1, const float* __restrict__ bv1,
    const float* __restrict__ bq2, const float* __restrict__ bk2, const float* __restrict__ bv2,
    const float* __restrict__ x, const float* __restrict__ enc,
    __half* __restrict__ wqkv, __half* __restrict__ wqo, __half* __restrict__ wkv,
    __half* __restrict__ wp1o, __half* __restrict__ wp2o,
    __half* __restrict__ wf1o, __half* __restrict__ wf2o,
    float* __restrict__ bqkv, float* __restrict__ bkv, float* __restrict__ bq2o,
    __half* __restrict__ xh, __half* __restrict__ ench)
{
    long long idx = (long long)blockIdx.x * 256 + threadIdx.x;
    if (idx >= PACK_TOTAL) return;
    const float scale = rsqrtf((float)EE);
    if (idx < S_ATTNW) {
        int reg = (int)(idx / HPK), i = (int)(idx % HPK);
        int h = i / (EE * HSS), e = (i / HSS) % EE, s = i % HSS;
        int out = h * HSS + s;
        float v; __half* dst; int rowoff;
        switch (reg) {
            case 0: v = wq1[i] * scale; dst = wqkv; rowoff = 0;      break;
            case 1: v = wk1[i];         dst = wqkv; rowoff = EE;     break;
            case 2: v = wv1[i];         dst = wqkv; rowoff = 2 * EE; break;
            case 3: v = wq2[i] * scale; dst = wqo;  rowoff = 0;      break;
            case 4: v = wk2[i];         dst = wkv;  rowoff = 0;      break;
            default: v = wv2[i];        dst = wkv;  rowoff = EE;     break;
        }
        dst[(size_t)(rowoff + out) * EE + e] = __float2half_rn(v);
        return;
    }
    idx -= S_ATTNW;
    if (idx < S_PROJ) {
        int reg = (int)(idx / HPK), i = (int)(idx % HPK);
        int e = i / EE, o = i % EE;
        (reg ? wp2o : wp1o)[(size_t)o * EE + e] = __float2half_rn((reg ? pw2 : pw1)[i]);
        return;
    }
    idx -= S_PROJ;
    if (idx < S_FF) {
        int e = (int)(idx / FFD), o = (int)(idx % FFD);
        wf1o[(size_t)o * EE + e] = __float2half_rn(fw1[idx]);
        return;
    }
    idx -= S_FF;
    if (idx < S_FF) {
        int e = (int)(idx / EE), o = (int)(idx % EE);
        wf2o[(size_t)o * FFD + e] = __float2half_rn(fw2[idx]);
        return;
    }
    idx -= S_FF;
    if (idx < 3 * EE) {
        int sub = (int)(idx / EE), jj = (int)(idx % EE);
        bqkv[idx] = sub == 0 ? bq1[jj] * scale : sub == 1 ? bk1[jj] : bv1[jj];
        return;
    }
    idx -= 3 * EE;
    if (idx < 2 * EE) { bkv[idx] = idx < EE ? bk2[idx] : bv2[idx - EE]; return; }
    idx -= 2 * EE;
    if (idx < EE) { bq2o[idx] = bq2[idx] * scale; return; }
    idx -= EE;
    const float* srcf; __half* dsth;
    if (idx < NACTV) { srcf = x; dsth = xh; }
    else { idx -= NACTV; srcf = enc; dsth = ench; }
    float4 v4 = ((const float4*)srcf)[idx];
    ((__half2*)dsth)[2 * idx]     = __floats2half2_rn(v4.x, v4.y);
    ((__half2*)dsth)[2 * idx + 1] = __floats2half2_rn(v4.z, v4.w);
}

// ---------------- fp16 tensor-core GEMM body --------------------------------
// C[N,M] = A[N,K] @ Wt[M,K]^T + bias (+resid) (opt relu). 128 x NT CTA tile.
template <int K, int NT>
__device__ __forceinline__ void load_chunk(uint32_t sbase,
                                           const __half* __restrict__ A,
                                           const __half* __restrict__ Wt,
                                           int row0, int col0, int tid,
                                           int stage, int kt) {
    constexpr uint32_t STRIDE = 16384u + NT * 128u;
    uint32_t sA = sbase + (uint32_t)stage * STRIDE;
    uint32_t sB = sA + 16384u;
#pragma unroll
    for (int i = 0; i < 4; i++) {
        int li = tid + i * 256; int r = li >> 3, sg = li & 7;
        cp16(sA + sw_off(r, sg), A + (size_t)(row0 + r) * K + kt + sg * 8);
    }
#pragma unroll
    for (int i = 0; i < NT / 32; i++) {
        int li = tid + i * 256; int r = li >> 3, sg = li & 7;
        cp16(sB + sw_off(r, sg), Wt + (size_t)(col0 + r) * K + kt + sg * 8);
    }
    asm volatile("cp.async.commit_group;");
}

template <int K, int NT>
__device__ __forceinline__ void gemm_body(const __half* __restrict__ A,
                                          const __half* __restrict__ Wt,
                                          const float* __restrict__ bias,
                                          const float* __restrict__ resid,
                                          float* __restrict__ Cf,
                                          __half* __restrict__ Ch,
                                          int M, int relu, int colt, int rowt,
                                          char* gsm)
{
    uint32_t sbase = smem_u32(gsm);
    constexpr uint32_t STRIDE = 16384u + NT * 128u;
    constexpr int MT = (NT == 128) ? 4 : 2;
    int tid = threadIdx.x, lane = tid & 31, warp = tid >> 5;
    int wm, wn;
    if (NT == 128) { wm = warp >> 2; wn = warp & 3; }
    else           { wm = warp >> 1; wn = warp & 1; }
    int gid = lane >> 2, tg = lane & 3;
    int j = lane >> 3, rr = lane & 7;
    int col0 = colt * NT, row0 = rowt * 128;

    float acc[MT][4][4];
#pragma unroll
    for (int a = 0; a < MT; a++)
#pragma unroll
        for (int b = 0; b < 4; b++)
#pragma unroll
            for (int c = 0; c < 4; c++) acc[a][b][c] = 0.0f;

    constexpr int nch = K >> 6;
    load_chunk<K, NT>(sbase, A, Wt, row0, col0, tid, 0, 0);
    load_chunk<K, NT>(sbase, A, Wt, row0, col0, tid, 1, 64);

#pragma unroll 2
    for (int it = 0; it < nch; it++) {
        if (it + 1 < nch) asm volatile("cp.async.wait_group 1;");
        else              asm volatile("cp.async.wait_group 0;");
        __syncthreads();
        if (it + 2 < nch)
            load_chunk<K, NT>(sbase, A, Wt, row0, col0, tid, (it + 2) % 3, (it + 2) * 64);
        uint32_t sA = sbase + (uint32_t)(it % 3) * STRIDE;
        uint32_t sB = sA + 16384u;
#pragma unroll
        for (int ks = 0; ks < 4; ks++) {
            uint32_t a[MT][4], bfr[2][4];
#pragma unroll
            for (int mt = 0; mt < MT; mt++)
                ldsm4(a[mt][0], a[mt][1], a[mt][2], a[mt][3],
                      sA + sw_off(wm * (16 * MT) + mt * 16 + (j & 1) * 8 + rr,
                                  ks * 2 + (j >> 1)));
#pragma unroll
            for (int p = 0; p < 2; p++)
                ldsm4(bfr[p][0], bfr[p][1], bfr[p][2], bfr[p][3],
                      sB + sw_off(wn * 32 + p * 16 + (j >> 1) * 8 + rr, ks * 2 + (j & 1)));
#pragma unroll
            for (int mt = 0; mt < MT; mt++)
#pragma unroll
                for (int nt = 0; nt < 4; nt++)
                    mma16816(acc[mt][nt], a[mt], &bfr[nt >> 1][(nt & 1) * 2]);
        }
    }

#pragma unroll
    for (int mt = 0; mt < MT; mt++)
#pragma unroll
        for (int nt = 0; nt < 4; nt++) {
            int r0 = row0 + wm * (16 * MT) + mt * 16 + gid;
            int c0 = col0 + wn * 32 + nt * 8 + tg * 2;
            float b0 = bias[c0], b1 = bias[c0 + 1];
            float v0 = acc[mt][nt][0] + b0, v1 = acc[mt][nt][1] + b1;
            float v2 = acc[mt][nt][2] + b0, v3 = acc[mt][nt][3] + b1;
            if (resid) {
                float2 ra = *(const float2*)(resid + (size_t)r0 * M + c0);
                float2 rb = *(const float2*)(resid + (size_t)(r0 + 8) * M + c0);
                v0 += ra.x; v1 += ra.y; v2 += rb.x; v3 += rb.y;
            }
            if (relu) {
                v0 = fmaxf(v0, 0.f); v1 = fmaxf(v1, 0.f);
                v2 = fmaxf(v2, 0.f); v3 = fmaxf(v3, 0.f);
            }
            if (Cf) {
                *(float2*)(Cf + (size_t)r0 * M + c0)       = make_float2(v0, v1);
                *(float2*)(Cf + (size_t)(r0 + 8) * M + c0) = make_float2(v2, v3);
            }
            if (Ch) {
                *(__half2*)(Ch + (size_t)r0 * M + c0)       = __floats2half2_rn(v0, v1);
                *(__half2*)(Ch + (size_t)(r0 + 8) * M + c0) = __floats2half2_rn(v2, v3);
            }
        }
}

template <int K, int NT>
__global__ void __launch_bounds__(256, 2)
gemm_std(const __half* __restrict__ A, const __half* __restrict__ Wt,
         const float* __restrict__ bias, const float* __restrict__ resid,
         float* __restrict__ Cf, __half* __restrict__ Ch, int M, int relu)
{
    extern __shared__ char gsm[];
    gemm_body<K, NT>(A, Wt, bias, resid, Cf, Ch, M, relu, blockIdx.x, blockIdx.y, gsm);
}

// merged q-proj + kv-proj (independent GEMMs, one launch, NT=64)
__global__ void __launch_bounds__(256, 2)
gemm_qkv2(const __half* __restrict__ A1, const __half* __restrict__ W1,
          const float* __restrict__ b1, __half* __restrict__ C1, int M1,
          const __half* __restrict__ A2, const __half* __restrict__ W2,
          const float* __restrict__ b2, __half* __restrict__ C2, int M2)
{
    extern __shared__ char gsm[];
    int t1 = M1 / 64;
    if ((int)blockIdx.x < t1)
        gemm_body<384, 64>(A1, W1, b1, nullptr, nullptr, C1, M1, 0,
                           blockIdx.x, blockIdx.y, gsm);
    else
        gemm_body<384, 64>(A2, W2, b2, nullptr, nullptr, C2, M2, 0,
                           blockIdx.x - t1, blockIdx.y, gsm);
}

// ---------------- flash attention: 128 q-rows per CTA, 8 warps --------------
#define AT_SMEM (16384 + 2 * 16384)   // Q 16KB + double-buffered K,V 2x16KB

__global__ void __launch_bounds__(256)
attn16_kernel(const __half* __restrict__ Qg, int ldq,
              const __half* __restrict__ Kg, const __half* __restrict__ Vg, int ldkv,
              __half* __restrict__ Og)
{
    extern __shared__ __align__(128) char asmem[];
    uint32_t sbase = smem_u32(asmem);
    uint32_t sQ = sbase;
    int tid = threadIdx.x, lane = tid & 31, w = tid >> 5;
    int gid = lane >> 2, tg = lane & 3;
    int j = lane >> 3, rr = lane & 7;

    int bid = blockIdx.x;
    int qt = bid & 1, h = (bid >> 1) % HH, b = bid / (2 * HH);
    int t0 = qt * 128;
    int hoff = h * HSS;

    const __half* qrow = Qg + (size_t)(b * TT + t0) * ldq + hoff;
#pragma unroll
    for (int i = 0; i < 4; i++) {
        int li = tid + i * 256; int r = li >> 3, sg = li & 7;
        cp16(sQ + sw_off(r, sg), qrow + (size_t)r * ldq + sg * 8);
    }
#define KVLOAD(ut, bufi)                                                           \
    {                                                                              \
        uint32_t sK_ = sbase + 16384u + (uint32_t)(bufi) * 16384u;                 \
        uint32_t sV_ = sK_ + 8192u;                                                \
        const __half* kr = Kg + (size_t)(b * TT + (ut) * 64) * ldkv + hoff;        \
        const __half* vr = Vg + (size_t)(b * TT + (ut) * 64) * ldkv + hoff;        \
        _Pragma("unroll")                                                          \
        for (int i = 0; i < 2; i++) {                                              \
            int li = tid + i * 256; int r = li >> 3, sg = li & 7;                  \
            cp16(sK_ + sw_off(r, sg), kr + (size_t)r * ldkv + sg * 8);             \
            cp16(sV_ + sw_off(r, sg), vr + (size_t)r * ldkv + sg * 8);             \
        }                                                                          \
        asm volatile("cp.async.commit_group;");                                    \
    }
    KVLOAD(0, 0);
    asm volatile("cp.async.wait_group 0;");
    __syncthreads();

    uint32_t qf[4][4];
#pragma unroll
    for (int ks = 0; ks < 4; ks++)
        ldsm4(qf[ks][0], qf[ks][1], qf[ks][2], qf[ks][3],
              sQ + sw_off(w * 16 + (j & 1) * 8 + rr, ks * 2 + (j >> 1)));

    float o[8][4];
#pragma unroll
    for (int nt = 0; nt < 8; nt++)
#pragma unroll
        for (int e = 0; e < 4; e++) o[nt][e] = 0.0f;
    float m0 = -1e30f, m1 = -1e30f, l0 = 0.0f, l1 = 0.0f;

    int nkv = 2 * (qt + 1);
    int r0g = t0 + w * 16 + gid;      // global row of acc slots 0/1; +8 for 2/3
    for (int ut = 0; ut < nkv; ut++) {
        if (ut > 0) { asm volatile("cp.async.wait_group 0;"); __syncthreads(); }
        if (ut < nkv - 1) KVLOAD(ut + 1, (ut + 1) & 1);
        uint32_t sK = sbase + 16384u + (uint32_t)(ut & 1) * 16384u;
        uint32_t sV = sK + 8192u;

        float s[8][4];
#pragma unroll
        for (int nt = 0; nt < 8; nt++)
#pragma unroll
            for (int e = 0; e < 4; e++) s[nt][e] = 0.0f;
#pragma unroll
        for (int ks = 0; ks < 4; ks++) {
            uint32_t kb[4][4];
#pragma unroll
            for (int p = 0; p < 4; p++)
                ldsm4(kb[p][0], kb[p][1], kb[p][2], kb[p][3],
                      sK + sw_off(p * 16 + (j >> 1) * 8 + rr, ks * 2 + (j & 1)));
#pragma unroll
            for (int nt = 0; nt < 8; nt++)
                mma16816(s[nt], qf[ks], &kb[nt >> 1][(nt & 1) * 2]);
        }
        if (ut >= 2 * qt) {   // causal boundary can cross this kv tile
#pragma unroll
            for (int nt = 0; nt < 8; nt++) {
                int u0 = ut * 64 + nt * 8 + tg * 2;
                if (u0     > r0g)     s[nt][0] = -1e30f;
                if (u0 + 1 > r0g)     s[nt][1] = -1e30f;
                if (u0     > r0g + 8) s[nt][2] = -1e30f;
                if (u0 + 1 > r0g + 8) s[nt][3] = -1e30f;
            }
        }
        float mx0 = -1e30f, mx1 = -1e30f;
#pragma unroll
        for (int nt = 0; nt < 8; nt++) {
            mx0 = fmaxf(mx0, fmaxf(s[nt][0], s[nt][1]));
            mx1 = fmaxf(mx1, fmaxf(s[nt][2], s[nt][3]));
        }
        mx0 = fmaxf(mx0, __shfl_xor_sync(~0u, mx0, 1));
        mx0 = fmaxf(mx0, __shfl_xor_sync(~0u, mx0, 2));
        mx1 = fmaxf(mx1, __shfl_xor_sync(~0u, mx1, 1));
        mx1 = fmaxf(mx1, __shfl_xor_sync(~0u, mx1, 2));
        float mn0 = fmaxf(m0, mx0), mn1 = fmaxf(m1, mx1);
        float f0 = __expf(m0 - mn0), f1 = __expf(m1 - mn1);
        m0 = mn0; m1 = mn1;
        float rs0 = 0.0f, rs1 = 0.0f;
#pragma unroll
        for (int nt = 0; nt < 8; nt++) {
            s[nt][0] = __expf(s[nt][0] - mn0); rs0 += s[nt][0];
            s[nt][1] = __expf(s[nt][1] - mn0); rs0 += s[nt][1];
            s[nt][2] = __expf(s[nt][2] - mn1); rs1 += s[nt][2];
            s[nt][3] = __expf(s[nt][3] - mn1); rs1 += s[nt][3];
        }
        rs0 += __shfl_xor_sync(~0u, rs0, 1); rs0 += __shfl_xor_sync(~0u, rs0, 2);
        rs1 += __shfl_xor_sync(~0u, rs1, 1); rs1 += __shfl_xor_sync(~0u, rs1, 2);
        l0 = l0 * f0 + rs0;
        l1 = l1 * f1 + rs1;
#pragma unroll
        for (int nt = 0; nt < 8; nt++) {
            o[nt][0] *= f0; o[nt][1] *= f0; o[nt][2] *= f1; o[nt][3] *= f1;
        }
        uint32_t pa[4][4];
#pragma unroll
        for (int kk = 0; kk < 4; kk++) {
            pa[kk][0] = ph2(s[2 * kk][0], s[2 * kk][1]);
            pa[kk][1] = ph2(s[2 * kk][2], s[2 * kk][3]);
            pa[kk][2] = ph2(s[2 * kk + 1][0], s[2 * kk + 1][1]);
            pa[kk][3] = ph2(s[2 * kk + 1][2], s[2 * kk + 1][3]);
        }
#pragma unroll
        for (int kk = 0; kk < 4; kk++) {
            uint32_t vb[4][4];
#pragma unroll
            for (int p = 0; p < 4; p++)
                ldsm4t(vb[p][0], vb[p][1], vb[p][2], vb[p][3],
                       sV + sw_off(kk * 16 + (j & 1) * 8 + rr, p * 2 + (j >> 1)));
#pragma unroll
            for (int nt = 0; nt < 8; nt++)
                mma16816(o[nt], pa[kk], &vb[nt >> 1][(nt & 1) * 2]);
        }
    }
    float i0 = 1.0f / l0, i1 = 1.0f / l1;
    __half* orow = Og + (size_t)(b * TT + t0) * EE + hoff;
#pragma unroll
    for (int nt = 0; nt < 8; nt++) {
        int c = nt * 8 + tg * 2;
        *(__half2*)(orow + (size_t)(w * 16 + gid) * EE + c) =
            __floats2half2_rn(o[nt][0] * i0, o[nt][1] * i0);
        *(__half2*)(orow + (size_t)(w * 16 + gid + 8) * EE + c) =
            __floats2half2_rn(o[nt][2] * i1, o[nt][3] * i1);
    }
}

// ---------------- LayerNorm: 2 rows per 256-thread block --------------------
__global__ void __launch_bounds__(256)
ln_kernel(const float* __restrict__ s_in,
          const float* __restrict__ g, const float* __restrict__ bt,
          float* __restrict__ o, __half* __restrict__ oh) {
    int half = threadIdx.x >> 7;
    int row = blockIdx.x * 2 + half;
    int tid = threadIdx.x & 127;
    int warp = threadIdx.x >> 5;
    float v[3];
#pragma unroll
    for (int i = 0; i < 3; i++)
        v[i] = s_in[(size_t)row * EE + tid + i * 128];
    __shared__ float red[8];
    float s = v[0] + v[1] + v[2];
#pragma unroll
    for (int off = 16; off; off >>= 1) s += __shfl_xor_sync(~0u, s, off);
    if ((threadIdx.x & 31) == 0) red[warp] = s;
    __syncthreads();
    int rb = half * 4;
    float mean = (red[rb] + red[rb + 1] + red[rb + 2] + red[rb + 3]) * (1.0f / EE);
    __syncthreads();
    float d0 = v[0] - mean, d1 = v[1] - mean, d2 = v[2] - mean;
    float sq = d0 * d0 + d1 * d1 + d2 * d2;
#pragma unroll
    for (int off = 16; off; off >>= 1) sq += __shfl_xor_sync(~0u, sq, off);
    if ((threadIdx.x & 31) == 0) red[warp] = sq;
    __syncthreads();
    float var = (red[rb] + red[rb + 1] + red[rb + 2] + red[rb + 3]) * (1.0f / EE);
    float inv = rsqrtf(var + 1e-5f);
#pragma unroll
    for (int i = 0; i < 3; i++) {
        int e = tid + i * 128;
        float val = (v[i] - mean) * inv * g[e] + bt[e];
        o[(size_t)row * EE + e] = val;
        if (oh) oh[(size_t)row * EE + e] = __float2half_rn(val);
    }
}

// ---------------- host orchestration ---------------------------------------
extern "C" void kernel_launch(void* const* d_in, const int* in_sizes, int n_in,
                              void* d_out, int out_size) {
    const float* enc = (const float*)d_in[0];
    const float* x   = (const float*)d_in[1];
    const float* sa1_wq = (const float*)d_in[2];
    const float* sa1_bq = (const float*)d_in[3];
    const float* sa1_wk = (const float*)d_in[4];
    const float* sa1_bk = (const float*)d_in[5];
    const float* sa1_wv = (const float*)d_in[6];
    const float* sa1_bv = (const float*)d_in[7];
    const float* sa1_pw = (const float*)d_in[8];
    const float* sa1_pb = (const float*)d_in[9];
    const float* sa2_wq = (const float*)d_in[10];
    const float* sa2_bq = (const float*)d_in[11];
    const float* sa2_wk = (const float*)d_in[12];
    const float* sa2_bk = (const float*)d_in[13];
    const float* sa2_wv = (const float*)d_in[14];
    const float* sa2_bv = (const float*)d_in[15];
    const float* sa2_pw = (const float*)d_in[16];
    const float* sa2_pb = (const float*)d_in[17];
    const float* ff_w1  = (const float*)d_in[18];
    const float* ff_b1  = (const float*)d_in[19];
    const float* ff_w2  = (const float*)d_in[20];
    const float* ff_b2  = (const float*)d_in[21];
    const float* ln1_g  = (const float*)d_in[22];
    const float* ln1_b  = (const float*)d_in[23];
    const float* ln2_g  = (const float*)d_in[24];
    const float* ln2_b  = (const float*)d_in[25];
    const float* ln3_g  = (const float*)d_in[26];
    const float* ln3_b  = (const float*)d_in[27];
    float* out = (float*)d_out;

    const int SM128 = 3 * 32768;          // NT=128: 96KB
    const int SM64  = 3 * 24576;          // NT=64 : 72KB
    cudaFuncSetAttribute(gemm_std<384, 128>,
                         cudaFuncAttributeMaxDynamicSharedMemorySize, SM128);
    cudaFuncSetAttribute(gemm_std<384, 64>,
                         cudaFuncAttributeMaxDynamicSharedMemorySize, SM64);
    cudaFuncSetAttribute(gemm_std<1536, 64>,
                         cudaFuncAttributeMaxDynamicSharedMemorySize, SM64);
    cudaFuncSetAttribute(gemm_qkv2,
                         cudaFuncAttributeMaxDynamicSharedMemorySize, SM64);
    cudaFuncSetAttribute(attn16_kernel,
                         cudaFuncAttributeMaxDynamicSharedMemorySize, AT_SMEM);

    __half *pqkv, *pkv, *pq, *patt, *phid, *pxh, *pench, *po1h, *po2h;
    __half *pwqkv, *pwq2, *pwkv, *pwp1, *pwp2, *pwf1, *pwf2;
    float *pbuf, *po1, *po2, *pbqkv, *pbkv, *pbq2;
    cudaGetSymbolAddress((void**)&pqkv,  g_qkv_h);
    cudaGetSymbolAddress((void**)&pkv,   g_kv_h);
    cudaGetSymbolAddress((void**)&pq,    g_q_h);
    cudaGetSymbolAddress((void**)&patt,  g_att_h);
    cudaGetSymbolAddress((void**)&phid,  g_hid_h);
    cudaGetSymbolAddress((void**)&pxh,   g_xh);
    cudaGetSymbolAddress((void**)&pench, g_ench);
    cudaGetSymbolAddress((void**)&po1h,  g_po1h);
    cudaGetSymbolAddress((void**)&po2h,  g_po2h);
    cudaGetSymbolAddress((void**)&pbuf,  g_buf);
    cudaGetSymbolAddress((void**)&po1,   g_o1);
    cudaGetSymbolAddress((void**)&po2,   g_o2);
    cudaGetSymbolAddress((void**)&pwqkv, g_wqkvh);
    cudaGetSymbolAddress((void**)&pwq2,  g_wq2h);
    cudaGetSymbolAddress((void**)&pwkv,  g_wkvh);
    cudaGetSymbolAddress((void**)&pwp1,  g_wp1h);
    cudaGetSymbolAddress((void**)&pwp2,  g_wp2h);
    cudaGetSymbolAddress((void**)&pwf1,  g_wf1h);
    cudaGetSymbolAddress((void**)&pwf2,  g_wf2h);
    cudaGetSymbolAddress((void**)&pbqkv, g_bqkv);
    cudaGetSymbolAddress((void**)&pbkv,  g_bkv);
    cudaGetSymbolAddress((void**)&pbq2,  g_bq2);

    megapack_kernel<<<(int)((PACK_TOTAL + 255) / 256), 256>>>(
        sa1_wq, sa1_wk, sa1_wv, sa2_wq, sa2_wk, sa2_wv,
        sa1_pw, sa2_pw, ff_w1, ff_w2,
        sa1_bq, sa1_bk, sa1_bv, sa2_bq, sa2_bk, sa2_bv,
        x, enc,
        pwqkv, pwq2, pwkv, pwp1, pwp2, pwf1, pwf2,
        pbqkv, pbkv, pbq2, pxh, pench);

    // ---- block 1: masked self-attention + add&norm ----
    gemm_std<384, 128><<<dim3(9, 128), 256, SM128>>>(
        pxh, pwqkv, pbqkv, nullptr, nullptr, pqkv, 3 * EE, 0);
    attn16_kernel<<<BB * HH * 2, 256, AT_SMEM>>>(pqkv, 3 * EE,
                                                 pqkv + EE, pqkv + 2 * EE, 3 * EE, patt);
    gemm_std<384, 64><<<dim3(6, 128), 256, SM64>>>(
        patt, pwp1, sa1_pb, x, pbuf, nullptr, EE, 0);           // pbuf = x + proj
    ln_kernel<<<NROWS / 2, 256>>>(pbuf, ln1_g, ln1_b, po1, po1h);

    // ---- block 2: cross-attention (still causal-masked) + add&norm ----
    gemm_qkv2<<<dim3(18, 128), 256, SM64>>>(
        po1h, pwq2, pbq2, pq, EE,
        pench, pwkv, pbkv, pkv, 2 * EE);
    attn16_kernel<<<BB * HH * 2, 256, AT_SMEM>>>(pq, EE,
                                                 pkv, pkv + EE, 2 * EE, patt);
    gemm_std<384, 64><<<dim3(6, 128), 256, SM64>>>(
        patt, pwp2, sa2_pb, po1, pbuf, nullptr, EE, 0);         // pbuf = o1 + proj
    ln_kernel<<<NROWS / 2, 256>>>(pbuf, ln2_g, ln2_b, po2, po2h);

    // ---- FFN + add&norm ----
    gemm_std<384, 128><<<dim3(12, 128), 256, SM128>>>(
        po2h, pwf1, ff_b1, nullptr, nullptr, phid, FFD, 1);
    gemm_std<1536, 64><<<dim3(6, 128), 256, SM64>>>(
        phid, pwf2, ff_b2, po2, pbuf, nullptr, EE, 0);          // pbuf = o2 + ff
    ln_kernel<<<NROWS / 2, 256>>>(pbuf, ln3_g, ln3_b, out, nullptr);
}

// round 9
// speedup vs baseline: 1.0728x; 1.0728x over previous
#include <cuda_runtime.h>
#include <cuda_fp16.h>
#include <cstdint>
#include <cstddef>

// Problem constants
#define EE   384
#define HH   6
#define HSS  64
#define BB   64
#define TT   256
#define FFD  1536
#define NROWS (BB*TT)          // 16384

// ---------------- scratch (device globals; no allocation allowed) ----------
__device__ __half g_qkv_h[(size_t)NROWS * 3 * EE];
__device__ __half g_kv_h[(size_t)NROWS * 2 * EE];
__device__ __half g_q_h[(size_t)NROWS * EE];
__device__ __half g_att_h[(size_t)NROWS * EE];
__device__ __half g_hid_h[(size_t)NROWS * FFD];
__device__ __half g_xh[(size_t)NROWS * EE];
__device__ __half g_ench[(size_t)NROWS * EE];
__device__ __half g_po1h[(size_t)NROWS * EE];
__device__ __half g_po2h[(size_t)NROWS * EE];
__device__ float  g_buf[(size_t)NROWS * EE];
__device__ float  g_o1[(size_t)NROWS * EE];
__device__ float  g_o2[(size_t)NROWS * EE];
// fp16 weights, transposed to [out][in]
__device__ __half g_wqkvh[3 * EE * EE];
__device__ __half g_wq2h[EE * EE];
__device__ __half g_wkvh[2 * EE * EE];
__device__ __half g_wp1h[EE * EE];
__device__ __half g_wp2h[EE * EE];
__device__ __half g_wf1h[FFD * EE];
__device__ __half g_wf2h[EE * FFD];
__device__ float  g_bqkv[3 * EE];
__device__ float  g_bkv[2 * EE];
__device__ float  g_bq2[EE];

// ---------------- PTX helpers ----------------------------------------------
__device__ __forceinline__ uint32_t smem_u32(const void* p) {
    uint32_t a;
    asm("{ .reg .u64 t; cvta.to.shared.u64 t, %1; cvt.u32.u64 %0, t; }" : "=r"(a) : "l"(p));
    return a;
}
__device__ __forceinline__ void cp16(uint32_t dst, const void* src) {
    asm volatile("cp.async.cg.shared.global [%0], [%1], 16;" :: "r"(dst), "l"(src));
}
__device__ __forceinline__ void ldsm4(uint32_t& r0, uint32_t& r1, uint32_t& r2, uint32_t& r3,
                                      uint32_t addr) {
    asm volatile("ldmatrix.sync.aligned.m8n8.x4.shared.b16 {%0,%1,%2,%3}, [%4];"
                 : "=r"(r0), "=r"(r1), "=r"(r2), "=r"(r3) : "r"(addr));
}
__device__ __forceinline__ void ldsm4t(uint32_t& r0, uint32_t& r1, uint32_t& r2, uint32_t& r3,
                                       uint32_t addr) {
    asm volatile("ldmatrix.sync.aligned.m8n8.x4.trans.shared.b16 {%0,%1,%2,%3}, [%4];"
                 : "=r"(r0), "=r"(r1), "=r"(r2), "=r"(r3) : "r"(addr));
}
__device__ __forceinline__ void mma16816(float* c, const uint32_t* a, const uint32_t* b) {
    asm volatile(
        "mma.sync.aligned.m16n8k16.row.col.f32.f16.f16.f32 "
        "{%0,%1,%2,%3}, {%4,%5,%6,%7}, {%8,%9}, {%0,%1,%2,%3};"
        : "+f"(c[0]), "+f"(c[1]), "+f"(c[2]), "+f"(c[3])
        : "r"(a[0]), "r"(a[1]), "r"(a[2]), "r"(a[3]), "r"(b[0]), "r"(b[1]));
}
__device__ __forceinline__ uint32_t ph2(float a, float b) {
    __half2 h = __floats2half2_rn(a, b);
    return *reinterpret_cast<uint32_t*>(&h);
}
__device__ __forceinline__ uint32_t sw_off(int r, int seg) {
    return (uint32_t)(r * 128 + (((seg ^ (r & 7)) & 7) << 4));
}

// ---------------- megapack --------------------------------------------------
#define HPK 147456
#define S_ATTNW (6*HPK)
#define S_PROJ  (2*HPK)
#define S_FF    (EE*FFD)
#define NACT    ((size_t)NROWS*EE)
#define NACTV   ((long long)(NACT/4))
#define PACK_TOTAL ((long long)S_ATTNW + S_PROJ + 2*S_FF + 3*EE + 2*EE + EE + 2*NACTV)

__global__ void megapack_kernel(
    const float* __restrict__ wq1, const float* __restrict__ wk1, const float* __restrict__ wv1,
    const float* __restrict__ wq2, const float* __restrict__ wk2, const float* __restrict__ wv2,
    const float* __restrict__ pw1, const float* __restrict__ pw2,
    const float* __restrict__ fw1, const float* __restrict__ fw2,
    const float* __restrict__ bq1, const float* __restrict__ bk1, const float* __restrict__ bv1,
    const float* __restrict__ bq2, const float* __restrict__ bk2, const float* __restrict__ bv2,
    const float* __restrict__ x, const float* __restrict__ enc,
    __half* __restrict__ wqkv, __half* __restrict__ wqo, __half* __restrict__ wkv,
    __half* __restrict__ wp1o, __half* __restrict__ wp2o,
    __half* __restrict__ wf1o, __half* __restrict__ wf2o,
    float* __restrict__ bqkv, float* __restrict__ bkv, float* __restrict__ bq2o,
    __half* __restrict__ xh, __half* __restrict__ ench)
{
    long long idx = (long long)blockIdx.x * 256 + threadIdx.x;
    if (idx >= PACK_TOTAL) return;
    const float scale = rsqrtf((float)EE);
    if (idx < S_ATTNW) {
        int reg = (int)(idx / HPK), i = (int)(idx % HPK);
        int h = i / (EE * HSS), e = (i / HSS) % EE, s = i % HSS;
        int out = h * HSS + s;
        float v; __half* dst; int rowoff;
        switch (reg) {
            case 0: v = wq1[i] * scale; dst = wqkv; rowoff = 0;      break;
            case 1: v = wk1[i];         dst = wqkv; rowoff = EE;     break;
            case 2: v = wv1[i];         dst = wqkv; rowoff = 2 * EE; break;
            case 3: v = wq2[i] * scale; dst = wqo;  rowoff = 0;      break;
            case 4: v = wk2[i];         dst = wkv;  rowoff = 0;      break;
            default: v = wv2[i];        dst = wkv;  rowoff = EE;     break;
        }
        dst[(size_t)(rowoff + out) * EE + e] = __float2half_rn(v);
        return;
    }
    idx -= S_ATTNW;
    if (idx < S_PROJ) {
        int reg = (int)(idx / HPK), i = (int)(idx % HPK);
        int e = i / EE, o = i % EE;
        (reg ? wp2o : wp1o)[(size_t)o * EE + e] = __float2half_rn((reg ? pw2 : pw1)[i]);
        return;
    }
    idx -= S_PROJ;
    if (idx < S_FF) {
        int e = (int)(idx / FFD), o = (int)(idx % FFD);
        wf1o[(size_t)o * EE + e] = __float2half_rn(fw1[idx]);
        return;
    }
    idx -= S_FF;
    if (idx < S_FF) {
        int e = (int)(idx / EE), o = (int)(idx % EE);
        wf2o[(size_t)o * FFD + e] = __float2half_rn(fw2[idx]);
        return;
    }
    idx -= S_FF;
    if (idx < 3 * EE) {
        int sub = (int)(idx / EE), jj = (int)(idx % EE);
        bqkv[idx] = sub == 0 ? bq1[jj] * scale : sub == 1 ? bk1[jj] : bv1[jj];
        return;
    }
    idx -= 3 * EE;
    if (idx < 2 * EE) { bkv[idx] = idx < EE ? bk2[idx] : bv2[idx - EE]; return; }
    idx -= 2 * EE;
    if (idx < EE) { bq2o[idx] = bq2[idx] * scale; return; }
    idx -= EE;
    const float* srcf; __half* dsth;
    if (idx < NACTV) { srcf = x; dsth = xh; }
    else { idx -= NACTV; srcf = enc; dsth = ench; }
    float4 v4 = ((const float4*)srcf)[idx];
    ((__half2*)dsth)[2 * idx]     = __floats2half2_rn(v4.x, v4.y);
    ((__half2*)dsth)[2 * idx + 1] = __floats2half2_rn(v4.z, v4.w);
}

// ---------------- fp16 tensor-core GEMM body (128x128 tile, BK=64) ----------
#define G16_SMEM (3 * 32768)

template <int K>
__device__ __forceinline__ void load_chunk(uint32_t sbase,
                                           const __half* __restrict__ A,
                                           const __half* __restrict__ Wt,
                                           int row0, int col0, int tid,
                                           int stage, int kt) {
    uint32_t sA = sbase + (uint32_t)stage * 32768u;
    uint32_t sB = sA + 16384u;
#pragma unroll
    for (int i = 0; i < 4; i++) {
        int li = tid + i * 256; int r = li >> 3, sg = li & 7;
        cp16(sA + sw_off(r, sg), A + (size_t)(row0 + r) * K + kt + sg * 8);
        cp16(sB + sw_off(r, sg), Wt + (size_t)(col0 + r) * K + kt + sg * 8);
    }
    asm volatile("cp.async.commit_group;");
}

template <int K>
__device__ __forceinline__ void gemm_body(const __half* __restrict__ A,
                                          const __half* __restrict__ Wt,
                                          const float* __restrict__ bias,
                                          const float* __restrict__ resid,
                                          float* __restrict__ Cf,
                                          __half* __restrict__ Ch,
                                          int M, int relu, int colt, int rowt,
                                          char* gsm)
{
    uint32_t sbase = smem_u32(gsm);
    int tid = threadIdx.x, lane = tid & 31, warp = tid >> 5;
    int wm = warp >> 2, wn = warp & 3;
    int gid = lane >> 2, tg = lane & 3;
    int j = lane >> 3, rr = lane & 7;
    int col0 = colt * 128, row0 = rowt * 128;

    float acc[4][4][4];
#pragma unroll
    for (int a = 0; a < 4; a++)
#pragma unroll
        for (int b = 0; b < 4; b++)
#pragma unroll
            for (int c = 0; c < 4; c++) acc[a][b][c] = 0.0f;

    constexpr int nch = K >> 6;
    load_chunk<K>(sbase, A, Wt, row0, col0, tid, 0, 0);
    load_chunk<K>(sbase, A, Wt, row0, col0, tid, 1, 64);

#pragma unroll 2
    for (int it = 0; it < nch; it++) {
        if (it + 1 < nch) asm volatile("cp.async.wait_group 1;");
        else              asm volatile("cp.async.wait_group 0;");
        __syncthreads();
        if (it + 2 < nch)
            load_chunk<K>(sbase, A, Wt, row0, col0, tid, (it + 2) % 3, (it + 2) * 64);
        uint32_t sA = sbase + (uint32_t)(it % 3) * 32768u;
        uint32_t sB = sA + 16384u;
#pragma unroll
        for (int ks = 0; ks < 4; ks++) {
            uint32_t a[4][4], bfr[2][4];
#pragma unroll
            for (int mt = 0; mt < 4; mt++)
                ldsm4(a[mt][0], a[mt][1], a[mt][2], a[mt][3],
                      sA + sw_off(wm * 64 + mt * 16 + (j & 1) * 8 + rr, ks * 2 + (j >> 1)));
#pragma unroll
            for (int p = 0; p < 2; p++)
                ldsm4(bfr[p][0], bfr[p][1], bfr[p][2], bfr[p][3],
                      sB + sw_off(wn * 32 + p * 16 + (j >> 1) * 8 + rr, ks * 2 + (j & 1)));
#pragma unroll
            for (int mt = 0; mt < 4; mt++)
#pragma unroll
                for (int nt = 0; nt < 4; nt++)
                    mma16816(acc[mt][nt], a[mt], &bfr[nt >> 1][(nt & 1) * 2]);
        }
    }

#pragma unroll
    for (int mt = 0; mt < 4; mt++)
#pragma unroll
        for (int nt = 0; nt < 4; nt++) {
            int r0 = row0 + wm * 64 + mt * 16 + gid;
            int c0 = col0 + wn * 32 + nt * 8 + tg * 2;
            float b0 = bias[c0], b1 = bias[c0 + 1];
            float v0 = acc[mt][nt][0] + b0, v1 = acc[mt][nt][1] + b1;
            float v2 = acc[mt][nt][2] + b0, v3 = acc[mt][nt][3] + b1;
            if (resid) {
                float2 ra = *(const float2*)(resid + (size_t)r0 * M + c0);
                float2 rb = *(const float2*)(resid + (size_t)(r0 + 8) * M + c0);
                v0 += ra.x; v1 += ra.y; v2 += rb.x; v3 += rb.y;
            }
            if (relu) {
                v0 = fmaxf(v0, 0.f); v1 = fmaxf(v1, 0.f);
                v2 = fmaxf(v2, 0.f); v3 = fmaxf(v3, 0.f);
            }
            if (Cf) {
                *(float2*)(Cf + (size_t)r0 * M + c0)       = make_float2(v0, v1);
                *(float2*)(Cf + (size_t)(r0 + 8) * M + c0) = make_float2(v2, v3);
            }
            if (Ch) {
                *(__half2*)(Ch + (size_t)r0 * M + c0)       = __floats2half2_rn(v0, v1);
                *(__half2*)(Ch + (size_t)(r0 + 8) * M + c0) = __floats2half2_rn(v2, v3);
            }
        }
}

template <int K>
__global__ void __launch_bounds__(256, 2)
gemm_std(const __half* __restrict__ A, const __half* __restrict__ Wt,
         const float* __restrict__ bias, const float* __restrict__ resid,
         float* __restrict__ Cf, __half* __restrict__ Ch, int M, int relu)
{
    extern __shared__ char gsm[];
    gemm_body<K>(A, Wt, bias, resid, Cf, Ch, M, relu, blockIdx.x, blockIdx.y, gsm);
}

// merged cross-attn q-proj + kv-proj (one launch, 128-col tiles)
__global__ void __launch_bounds__(256, 2)
gemm_qkv2(const __half* __restrict__ A1, const __half* __restrict__ W1,
          const float* __restrict__ b1, __half* __restrict__ C1, int M1,
          const __half* __restrict__ A2, const __half* __restrict__ W2,
          const float* __restrict__ b2, __half* __restrict__ C2, int M2)
{
    extern __shared__ char gsm[];
    int t1 = M1 / 128;
    if ((int)blockIdx.x < t1)
        gemm_body<384>(A1, W1, b1, nullptr, nullptr, C1, M1, 0,
                       blockIdx.x, blockIdx.y, gsm);
    else
        gemm_body<384>(A2, W2, b2, nullptr, nullptr, C2, M2, 0,
                       blockIdx.x - t1, blockIdx.y, gsm);
}

// ---------------- flash attention: 128 q-rows per CTA, 8 warps --------------
#define AT_SMEM (16384 + 2 * 16384)

__global__ void __launch_bounds__(256, 2)
attn16_kernel(const __half* __restrict__ Qg, int ldq,
              const __half* __restrict__ Kg, const __half* __restrict__ Vg, int ldkv,
              __half* __restrict__ Og)
{
    extern __shared__ __align__(128) char asmem[];
    uint32_t sbase = smem_u32(asmem);
    uint32_t sQ = sbase;
    int tid = threadIdx.x, lane = tid & 31, w = tid >> 5;
    int gid = lane >> 2, tg = lane & 3;
    int j = lane >> 3, rr = lane & 7;

    int bid = blockIdx.x;
    int qt = bid & 1, h = (bid >> 1) % HH, b = bid / (2 * HH);
    int t0 = qt * 128;
    int hoff = h * HSS;

    const __half* qrow = Qg + (size_t)(b * TT + t0) * ldq + hoff;
#pragma unroll
    for (int i = 0; i < 4; i++) {
        int li = tid + i * 256; int r = li >> 3, sg = li & 7;
        cp16(sQ + sw_off(r, sg), qrow + (size_t)r * ldq + sg * 8);
    }
#define KVLOAD(ut, bufi)                                                           \
    {                                                                              \
        uint32_t sK_ = sbase + 16384u + (uint32_t)(bufi) * 16384u;                 \
        uint32_t sV_ = sK_ + 8192u;                                                \
        const __half* kr = Kg + (size_t)(b * TT + (ut) * 64) * ldkv + hoff;        \
        const __half* vr = Vg + (size_t)(b * TT + (ut) * 64) * ldkv + hoff;        \
        _Pragma("unroll")                                                          \
        for (int i = 0; i < 2; i++) {                                              \
            int li = tid + i * 256; int r = li >> 3, sg = li & 7;                  \
            cp16(sK_ + sw_off(r, sg), kr + (size_t)r * ldkv + sg * 8);             \
            cp16(sV_ + sw_off(r, sg), vr + (size_t)r * ldkv + sg * 8);             \
        }                                                                          \
        asm volatile("cp.async.commit_group;");                                    \
    }
    KVLOAD(0, 0);
    asm volatile("cp.async.wait_group 0;");
    __syncthreads();

    uint32_t qf[4][4];
#pragma unroll
    for (int ks = 0; ks < 4; ks++)
        ldsm4(qf[ks][0], qf[ks][1], qf[ks][2], qf[ks][3],
              sQ + sw_off(w * 16 + (j & 1) * 8 + rr, ks * 2 + (j >> 1)));

    float o[8][4];
#pragma unroll
    for (int nt = 0; nt < 8; nt++)
#pragma unroll
        for (int e = 0; e < 4; e++) o[nt][e] = 0.0f;
    float m0 = -1e30f, m1 = -1e30f, l0 = 0.0f, l1 = 0.0f;

    int nkv = 2 * (qt + 1);
    int r0g = t0 + w * 16 + gid;
    for (int ut = 0; ut < nkv; ut++) {
        if (ut > 0) { asm volatile("cp.async.wait_group 0;"); __syncthreads(); }
        if (ut < nkv - 1) KVLOAD(ut + 1, (ut + 1) & 1);
        uint32_t sK = sbase + 16384u + (uint32_t)(ut & 1) * 16384u;
        uint32_t sV = sK + 8192u;

        float s[8][4];
#pragma unroll
        for (int nt = 0; nt < 8; nt++)
#pragma unroll
            for (int e = 0; e < 4; e++) s[nt][e] = 0.0f;
#pragma unroll
        for (int ks = 0; ks < 4; ks++) {
            uint32_t kb[4][4];
#pragma unroll
            for (int p = 0; p < 4; p++)
                ldsm4(kb[p][0], kb[p][1], kb[p][2], kb[p][3],
                      sK + sw_off(p * 16 + (j >> 1) * 8 + rr, ks * 2 + (j & 1)));
#pragma unroll
            for (int nt = 0; nt < 8; nt++)
                mma16816(s[nt], qf[ks], &kb[nt >> 1][(nt & 1) * 2]);
        }
        if (ut >= 2 * qt) {
#pragma unroll
            for (int nt = 0; nt < 8; nt++) {
                int u0 = ut * 64 + nt * 8 + tg * 2;
                if (u0     > r0g)     s[nt][0] = -1e30f;
                if (u0 + 1 > r0g)     s[nt][1] = -1e30f;
                if (u0     > r0g + 8) s[nt][2] = -1e30f;
                if (u0 + 1 > r0g + 8) s[nt][3] = -1e30f;
            }
        }
        float mx0 = -1e30f, mx1 = -1e30f;
#pragma unroll
        for (int nt = 0; nt < 8; nt++) {
            mx0 = fmaxf(mx0, fmaxf(s[nt][0], s[nt][1]));
            mx1 = fmaxf(mx1, fmaxf(s[nt][2], s[nt][3]));
        }
        mx0 = fmaxf(mx0, __shfl_xor_sync(~0u, mx0, 1));
        mx0 = fmaxf(mx0, __shfl_xor_sync(~0u, mx0, 2));
        mx1 = fmaxf(mx1, __shfl_xor_sync(~0u, mx1, 1));
        mx1 = fmaxf(mx1, __shfl_xor_sync(~0u, mx1, 2));
        float mn0 = fmaxf(m0, mx0), mn1 = fmaxf(m1, mx1);
        float f0 = __expf(m0 - mn0), f1 = __expf(m1 - mn1);
        m0 = mn0; m1 = mn1;
        float rs0 = 0.0f, rs1 = 0.0f;
#pragma unroll
        for (int nt = 0; nt < 8; nt++) {
            s[nt][0] = __expf(s[nt][0] - mn0); rs0 += s[nt][0];
            s[nt][1] = __expf(s[nt][1] - mn0); rs0 += s[nt][1];
            s[nt][2] = __expf(s[nt][2] - mn1); rs1 += s[nt][2];
            s[nt][3] = __expf(s[nt][3] - mn1); rs1 += s[nt][3];
        }
        rs0 += __shfl_xor_sync(~0u, rs0, 1); rs0 += __shfl_xor_sync(~0u, rs0, 2);
        rs1 += __shfl_xor_sync(~0u, rs1, 1); rs1 += __shfl_xor_sync(~0u, rs1, 2);
        l0 = l0 * f0 + rs0;
        l1 = l1 * f1 + rs1;
#pragma unroll
        for (int nt = 0; nt < 8; nt++) {
            o[nt][0] *= f0; o[nt][1] *= f0; o[nt][2] *= f1; o[nt][3] *= f1;
        }
        uint32_t pa[4][4];
#pragma unroll
        for (int kk = 0; kk < 4; kk++) {
            pa[kk][0] = ph2(s[2 * kk][0], s[2 * kk][1]);
            pa[kk][1] = ph2(s[2 * kk][2], s[2 * kk][3]);
            pa[kk][2] = ph2(s[2 * kk + 1][0], s[2 * kk + 1][1]);
            pa[kk][3] = ph2(s[2 * kk + 1][2], s[2 * kk + 1][3]);
        }
#pragma unroll
        for (int kk = 0; kk < 4; kk++) {
            uint32_t vb[4][4];
#pragma unroll
            for (int p = 0; p < 4; p++)
                ldsm4t(vb[p][0], vb[p][1], vb[p][2], vb[p][3],
                       sV + sw_off(kk * 16 + (j & 1) * 8 + rr, p * 2 + (j >> 1)));
#pragma unroll
            for (int nt = 0; nt < 8; nt++)
                mma16816(o[nt], pa[kk], &vb[nt >> 1][(nt & 1) * 2]);
        }
    }
    float i0 = 1.0f / l0, i1 = 1.0f / l1;
    __half* orow = Og + (size_t)(b * TT + t0) * EE + hoff;
#pragma unroll
    for (int nt = 0; nt < 8; nt++) {
        int c = nt * 8 + tg * 2;
        *(__half2*)(orow + (size_t)(w * 16 + gid) * EE + c) =
            __floats2half2_rn(o[nt][0] * i0, o[nt][1] * i0);
        *(__half2*)(orow + (size_t)(w * 16 + gid + 8) * EE + c) =
            __floats2half2_rn(o[nt][2] * i1, o[nt][3] * i1);
    }
}

// ---------------- LayerNorm: one warp per row, float4, shuffle-only ---------
__global__ void __launch_bounds__(256)
ln_kernel(const float* __restrict__ s_in,
          const float* __restrict__ g, const float* __restrict__ bt,
          float* __restrict__ o, __half* __restrict__ oh) {
    int warp = threadIdx.x >> 5, lane = threadIdx.x & 31;
    int row = blockIdx.x * 8 + warp;
    const float4* rp = (const float4*)(s_in + (size_t)row * EE);
    float4 v[3];
#pragma unroll
    for (int i = 0; i < 3; i++) v[i] = rp[lane + 32 * i];
    float s = 0.0f;
#pragma unroll
    for (int i = 0; i < 3; i++) s += v[i].x + v[i].y + v[i].z + v[i].w;
#pragma unroll
    for (int off = 16; off; off >>= 1) s += __shfl_xor_sync(~0u, s, off);
    float mean = s * (1.0f / EE);
    float sq = 0.0f;
#pragma unroll
    for (int i = 0; i < 3; i++) {
        float a0 = v[i].x - mean, a1 = v[i].y - mean;
        float a2 = v[i].z - mean, a3 = v[i].w - mean;
        sq += a0 * a0 + a1 * a1 + a2 * a2 + a3 * a3;
    }
#pragma unroll
    for (int off = 16; off; off >>= 1) sq += __shfl_xor_sync(~0u, sq, off);
    float inv = rsqrtf(sq * (1.0f / EE) + 1e-5f);
    float4* op = (float4*)(o + (size_t)row * EE);
    __half2* ohp = oh ? (__half2*)(oh + (size_t)row * EE) : nullptr;
#pragma unroll
    for (int i = 0; i < 3; i++) {
        int e4 = lane + 32 * i;
        float4 gg = *(const float4*)(g + e4 * 4);
        float4 bb = *(const float4*)(bt + e4 * 4);
        float4 r;
        r.x = (v[i].x - mean) * inv * gg.x + bb.x;
        r.y = (v[i].y - mean) * inv * gg.y + bb.y;
        r.z = (v[i].z - mean) * inv * gg.z + bb.z;
        r.w = (v[i].w - mean) * inv * gg.w + bb.w;
        op[e4] = r;
        if (ohp) {
            ohp[e4 * 2]     = __floats2half2_rn(r.x, r.y);
            ohp[e4 * 2 + 1] = __floats2half2_rn(r.z, r.w);
        }
    }
}

// ---------------- host orchestration ---------------------------------------
extern "C" void kernel_launch(void* const* d_in, const int* in_sizes, int n_in,
                              void* d_out, int out_size) {
    const float* enc = (const float*)d_in[0];
    const float* x   = (const float*)d_in[1];
    const float* sa1_wq = (const float*)d_in[2];
    const float* sa1_bq = (const float*)d_in[3];
    const float* sa1_wk = (const float*)d_in[4];
    const float* sa1_bk = (const float*)d_in[5];
    const float* sa1_wv = (const float*)d_in[6];
    const float* sa1_bv = (const float*)d_in[7];
    const float* sa1_pw = (const float*)d_in[8];
    const float* sa1_pb = (const float*)d_in[9];
    const float* sa2_wq = (const float*)d_in[10];
    const float* sa2_bq = (const float*)d_in[11];
    const float* sa2_wk = (const float*)d_in[12];
    const float* sa2_bk = (const float*)d_in[13];
    const float* sa2_wv = (const float*)d_in[14];
    const float* sa2_bv = (const float*)d_in[15];
    const float* sa2_pw = (const float*)d_in[16];
    const float* sa2_pb = (const float*)d_in[17];
    const float* ff_w1  = (const float*)d_in[18];
    const float* ff_b1  = (const float*)d_in[19];
    const float* ff_w2  = (const float*)d_in[20];
    const float* ff_b2  = (const float*)d_in[21];
    const float* ln1_g  = (const float*)d_in[22];
    const float* ln1_b  = (const float*)d_in[23];
    const float* ln2_g  = (const float*)d_in[24];
    const float* ln2_b  = (const float*)d_in[25];
    const float* ln3_g  = (const float*)d_in[26];
    const float* ln3_b  = (const float*)d_in[27];
    float* out = (float*)d_out;

    cudaFuncSetAttribute(gemm_std<384>,
                         cudaFuncAttributeMaxDynamicSharedMemorySize, G16_SMEM);
    cudaFuncSetAttribute(gemm_std<1536>,
                         cudaFuncAttributeMaxDynamicSharedMemorySize, G16_SMEM);
    cudaFuncSetAttribute(gemm_qkv2,
                         cudaFuncAttributeMaxDynamicSharedMemorySize, G16_SMEM);
    cudaFuncSetAttribute(attn16_kernel,
                         cudaFuncAttributeMaxDynamicSharedMemorySize, AT_SMEM);

    __half *pqkv, *pkv, *pq, *patt, *phid, *pxh, *pench, *po1h, *po2h;
    __half *pwqkv, *pwq2, *pwkv, *pwp1, *pwp2, *pwf1, *pwf2;
    float *pbuf, *po1, *po2, *pbqkv, *pbkv, *pbq2;
    cudaGetSymbolAddress((void**)&pqkv,  g_qkv_h);
    cudaGetSymbolAddress((void**)&pkv,   g_kv_h);
    cudaGetSymbolAddress((void**)&pq,    g_q_h);
    cudaGetSymbolAddress((void**)&patt,  g_att_h);
    cudaGetSymbolAddress((void**)&phid,  g_hid_h);
    cudaGetSymbolAddress((void**)&pxh,   g_xh);
    cudaGetSymbolAddress((void**)&pench, g_ench);
    cudaGetSymbolAddress((void**)&po1h,  g_po1h);
    cudaGetSymbolAddress((void**)&po2h,  g_po2h);
    cudaGetSymbolAddress((void**)&pbuf,  g_buf);
    cudaGetSymbolAddress((void**)&po1,   g_o1);
    cudaGetSymbolAddress((void**)&po2,   g_o2);
    cudaGetSymbolAddress((void**)&pwqkv, g_wqkvh);
    cudaGetSymbolAddress((void**)&pwq2,  g_wq2h);
    cudaGetSymbolAddress((void**)&pwkv,  g_wkvh);
    cudaGetSymbolAddress((void**)&pwp1,  g_wp1h);
    cudaGetSymbolAddress((void**)&pwp2,  g_wp2h);
    cudaGetSymbolAddress((void**)&pwf1,  g_wf1h);
    cudaGetSymbolAddress((void**)&pwf2,  g_wf2h);
    cudaGetSymbolAddress((void**)&pbqkv, g_bqkv);
    cudaGetSymbolAddress((void**)&pbkv,  g_bkv);
    cudaGetSymbolAddress((void**)&pbq2,  g_bq2);

    megapack_kernel<<<(int)((PACK_TOTAL + 255) / 256), 256>>>(
        sa1_wq, sa1_wk, sa1_wv, sa2_wq, sa2_wk, sa2_wv,
        sa1_pw, sa2_pw, ff_w1, ff_w2,
        sa1_bq, sa1_bk, sa1_bv, sa2_bq, sa2_bk, sa2_bv,
        x, enc,
        pwqkv, pwq2, pwkv, pwp1, pwp2, pwf1, pwf2,
        pbqkv, pbkv, pbq2, pxh, pench);

    // ---- block 1: masked self-attention + add&norm ----
    gemm_std<384><<<dim3(9, 128), 256, G16_SMEM>>>(
        pxh, pwqkv, pbqkv, nullptr, nullptr, pqkv, 3 * EE, 0);
    attn16_kernel<<<BB * HH * 2, 256, AT_SMEM>>>(pqkv, 3 * EE,
                                                 pqkv + EE, pqkv + 2 * EE, 3 * EE, patt);
    gemm_std<384><<<dim3(3, 128), 256, G16_SMEM>>>(
        patt, pwp1, sa1_pb, x, pbuf, nullptr, EE, 0);           // pbuf = x + proj
    ln_kernel<<<NROWS / 8, 256>>>(pbuf, ln1_g, ln1_b, po1, po1h);

    // ---- block 2: cross-attention (still causal-masked) + add&norm ----
    gemm_qkv2<<<dim3(9, 128), 256, G16_SMEM>>>(
        po1h, pwq2, pbq2, pq, EE,
        pench, pwkv, pbkv, pkv, 2 * EE);
    attn16_kernel<<<BB * HH * 2, 256, AT_SMEM>>>(pq, EE,
                                                 pkv, pkv + EE, 2 * EE, patt);
    gemm_std<384><<<dim3(3, 128), 256, G16_SMEM>>>(
        patt, pwp2, sa2_pb, po1, pbuf, nullptr, EE, 0);         // pbuf = o1 + proj
    ln_kernel<<<NROWS / 8, 256>>>(pbuf, ln2_g, ln2_b, po2, po2h);

    // ---- FFN + add&norm ----
    gemm_std<384><<<dim3(12, 128), 256, G16_SMEM>>>(
        po2h, pwf1, ff_b1, nullptr, nullptr, phid, FFD, 1);
    gemm_std<1536><<<dim3(3, 128), 256, G16_SMEM>>>(
        phid, pwf2, ff_b2, po2, pbuf, nullptr, EE, 0);          // pbuf = o2 + ff
    ln_kernel<<<NROWS / 8, 256>>>(pbuf, ln3_g, ln3_b, out, nullptr);
}